// round 10
// baseline (speedup 1.0000x reference)
#include <cuda_runtime.h>
#include <cuda_fp16.h>
#include <cstdint>
#include <math.h>

// Problem constants
#define Bsz  4
#define Nseq 8192
#define Dm   1024
#define Hh   8
#define HDim 128
#define BH   (Bsz*Hh)        // 32
#define Mrows (Bsz*Nseq)     // 32768
#define K3   (3*Dm)          // 3072 output cols
#define KA   1024            // single-segment fp16 contraction
#define NCH2 16              // kv n-chunks

// ---------------- scratch (static device globals; no allocations) -------------
__device__ __half g_a2[(size_t)Mrows*KA];      // 64 MiB  fp16(x_n)
__device__ __half g_wt[(size_t)K3*KA];         // 6 MiB   fp16(w*gamma), transposed
__device__ float g_cbias[K3];
__device__ __half g_qhi[(size_t)BH*Nseq*HDim]; // [bh][n][d]
__device__ __half g_qlo[(size_t)BH*Nseq*HDim];
__device__ __half g_kth[(size_t)BH*HDim*Nseq]; // [bh][d][n] transposed
__device__ __half g_ktl[(size_t)BH*HDim*Nseq];
__device__ __half g_vth[(size_t)BH*HDim*Nseq];
__device__ __half g_vtl[(size_t)BH*HDim*Nseq];
__device__ float g_kvp[(size_t)BH*NCH2*HDim*HDim];    // 33.5 MiB partials
__device__ __half g_kvt2[(size_t)BH*HDim*384]; // [bh][e][hi|hi|lo over d]
__device__ unsigned char g_mask[Bsz*Nseq];

// ---------------- 1) fused mask probe + normalize (single block) --------------
__global__ void mask_all_kernel(const unsigned int* __restrict__ m) {
    __shared__ unsigned int flag;
    if (threadIdx.x == 0) flag = 0u;
    __syncthreads();
    unsigned int loc = 0;
    #pragma unroll
    for (int i = threadIdx.x; i < 8192; i += 1024) loc |= (m[i] > 1u);
    if (loc) atomicOr(&flag, 1u);
    __syncthreads();
    const bool bytelay = (flag != 0u);
    for (int i = threadIdx.x; i < Bsz*Nseq; i += 1024)
        g_mask[i] = bytelay ? (((const unsigned char*)m)[i] ? 1 : 0)
                            : (((const int*)m)[i]           ? 1 : 0);
}

// ---------------- 2) fused LN stats + A2 (fp16) build -------------------------
__global__ void ln_a2_kernel(const float* __restrict__ x) {
    int row = blockIdx.x;
    float4 v = reinterpret_cast<const float4*>(x)[(size_t)row*(Dm/4) + threadIdx.x];
    float s  = v.x+v.y+v.z+v.w;
    float ss = v.x*v.x+v.y*v.y+v.z*v.z+v.w*v.w;
    __shared__ float sh[8], sh2[8];
    __shared__ float s_mu, s_rs;
    #pragma unroll
    for (int o=16;o;o>>=1){ s+=__shfl_down_sync(~0u,s,o); ss+=__shfl_down_sync(~0u,ss,o); }
    int w = threadIdx.x>>5, l = threadIdx.x&31;
    if (l==0){ sh[w]=s; sh2[w]=ss; }
    __syncthreads();
    if (threadIdx.x < 8) {
        s = sh[threadIdx.x]; ss = sh2[threadIdx.x];
        #pragma unroll
        for (int o=4;o;o>>=1){ s+=__shfl_down_sync(0xffu,s,o); ss+=__shfl_down_sync(0xffu,ss,o); }
        if (threadIdx.x==0){
            float m = s*(1.0f/Dm);
            float var = ss*(1.0f/Dm) - m*m;
            s_mu = m; s_rs = rsqrtf(var + 1e-5f);
        }
    }
    __syncthreads();
    float mu = s_mu, rs = s_rs;
    float n0=(v.x-mu)*rs, n1=(v.y-mu)*rs, n2=(v.z-mu)*rs, n3=(v.w-mu)*rs;
    __half2 hp0{__float2half_rn(n0), __float2half_rn(n1)};
    __half2 hp1{__float2half_rn(n2), __float2half_rn(n3)};
    uint2 hw{*(uint32_t*)&hp0, *(uint32_t*)&hp1};
    ((uint2*)(g_a2 + (size_t)row*KA))[threadIdx.x] = hw;
}

// ---------------- 3) Wt build + colbias (fused, deterministic) ----------------
__global__ void __launch_bounds__(256) build_wt_cb_kernel(
    const float* __restrict__ w, const float* __restrict__ gamma,
    const float* __restrict__ beta)
{
    __shared__ float tile[32][33];
    __shared__ float cbpart[8][32];
    const int n0 = blockIdx.x*32;
    const int tx = threadIdx.x & 31, ty = threadIdx.x >> 5;
    float cb = 0.f;
    for (int k0 = 0; k0 < Dm; k0 += 32) {
        #pragma unroll
        for (int r=0;r<4;r++){
            int kk = ty + r*8;
            float raw = w[(size_t)(k0+kk)*K3 + n0 + tx];
            cb += beta[k0+kk]*raw;
            tile[kk][tx] = raw * gamma[k0+kk];
        }
        __syncthreads();
        #pragma unroll
        for (int r=0;r<4;r++){
            int nn = ty + r*8;
            g_wt[(size_t)(n0+nn)*KA + k0 + tx] = __float2half_rn(tile[tx][nn]);
        }
        __syncthreads();
    }
    cbpart[ty][tx] = cb;
    __syncthreads();
    if (ty == 0) {
        float s = 0.f;
        #pragma unroll
        for (int r=0;r<8;r++) s += cbpart[r][tx];
        g_cbias[n0+tx] = s;
    }
}

// ================= mma.sync building blocks ====================================
#define LDS_PAD 72
#define TILE_B  18432        // 128*72*2
#define STAGE_B 36864
#define NSTAGE  3
#define SMEM_SZ (NSTAGE*STAGE_B)   // 110592

__device__ __forceinline__ uint32_t smem_u32(const void* p) {
    uint32_t a;
    asm("{ .reg .u64 t; cvta.to.shared.u64 t, %1; cvt.u32.u64 %0, t; }" : "=r"(a) : "l"(p));
    return a;
}
__device__ __forceinline__ void cp16(uint32_t s, const void* g) {
    asm volatile("cp.async.cg.shared.global [%0], [%1], 16;" :: "r"(s), "l"(g));
}
__device__ __forceinline__ void cp_commit() {
    asm volatile("cp.async.commit_group;" ::: "memory");
}
__device__ __forceinline__ void ldmatrix_x4(uint32_t* r, uint32_t a) {
    asm volatile("ldmatrix.sync.aligned.m8n8.x4.shared.b16 {%0,%1,%2,%3}, [%4];"
                 : "=r"(r[0]), "=r"(r[1]), "=r"(r[2]), "=r"(r[3]) : "r"(a));
}
__device__ __forceinline__ void mma16816(float* d, const uint32_t* a, const uint32_t* b) {
    asm volatile("mma.sync.aligned.m16n8k16.row.col.f32.f16.f16.f32 "
                 "{%0,%1,%2,%3}, {%4,%5,%6,%7}, {%8,%9}, {%0,%1,%2,%3};"
                 : "+f"(d[0]), "+f"(d[1]), "+f"(d[2]), "+f"(d[3])
                 : "r"(a[0]), "r"(a[1]), "r"(a[2]), "r"(a[3]), "r"(b[0]), "r"(b[1]));
}

// Fill one 128x64 fp16 tile into padded smem: 256-thread variant (4 cp16/thr).
__device__ __forceinline__ void fill_tile(uint32_t sdst, const __half* __restrict__ g,
                                          size_t ld, int tid) {
    #pragma unroll
    for (int i=0;i<4;i++){
        int c = tid + i*256;
        int row = c>>3, col = (c&7)*8;
        cp16(sdst + (uint32_t)(row*LDS_PAD + col)*2, g + (size_t)row*ld + col);
    }
}
// 128-thread variant (8 cp16/thr).
__device__ __forceinline__ void fill_tile128(uint32_t sdst, const __half* __restrict__ g,
                                             size_t ld, int tid) {
    #pragma unroll
    for (int i=0;i<8;i++){
        int c = tid + i*128;
        int row = c>>3, col = (c&7)*8;
        cp16(sdst + (uint32_t)(row*LDS_PAD + col)*2, g + (size_t)row*ld + col);
    }
}

// ---- 8-warp (2x4) config: warp tile 64x32 (kv/out kernels) ----
#define MMA_BK64(sa, sb)                                                          \
    do {                                                                          \
        _Pragma("unroll")                                                         \
        for (int ks = 0; ks < 4; ks++) {                                          \
            const int kk = ks*16;                                                 \
            uint32_t afr[4][4];                                                   \
            _Pragma("unroll")                                                     \
            for (int mt=0;mt<4;mt++)                                              \
                ldmatrix_x4(afr[mt], (sa) + (uint32_t)((M0 + mt*16 + a_m)*LDS_PAD + kk + a_k)*2); \
            uint32_t bfr[2][4];                                                   \
            _Pragma("unroll")                                                     \
            for (int nh=0;nh<2;nh++)                                              \
                ldmatrix_x4(bfr[nh], (sb) + (uint32_t)((N0 + nh*16 + b_n)*LDS_PAD + kk + b_k)*2); \
            _Pragma("unroll")                                                     \
            for (int mt=0;mt<4;mt++)                                              \
                _Pragma("unroll")                                                 \
                for (int nt=0;nt<4;nt++)                                          \
                    mma16816(acc[mt][nt], afr[mt], &bfr[nt>>1][(nt&1)*2]);        \
        }                                                                         \
    } while (0)

#define WARP_VARS                                                                 \
    const int w  = tid>>5, lane = tid&31;                                         \
    const int wm = w>>2, wn = w&3;                                                \
    const int M0 = wm*64, N0 = wn*32;                                             \
    const int a_m = (lane&7) + ((lane>>3)&1)*8;                                   \
    const int a_k = (lane>>4)*8;                                                  \
    const int b_n = (lane&7) + (lane>>4)*8;                                       \
    const int b_k = ((lane>>3)&1)*8;                                              \
    float acc[4][4][4];                                                           \
    _Pragma("unroll")                                                             \
    for (int i=0;i<4;i++)                                                         \
        _Pragma("unroll")                                                         \
        for (int j=0;j<4;j++)                                                     \
            _Pragma("unroll")                                                     \
            for (int r=0;r<4;r++) acc[i][j][r]=0.f;

// ---- 4-warp (2x2) config: warp tile 64x64 (qkv kernel) ----
#define WARP_VARS4                                                                \
    const int w  = tid>>5, lane = tid&31;                                         \
    const int wm = w>>1, wn = w&1;                                                \
    const int M0 = wm*64, N0 = wn*64;                                             \
    const int a_m = (lane&7) + ((lane>>3)&1)*8;                                   \
    const int a_k = (lane>>4)*8;                                                  \
    const int b_n = (lane&7) + (lane>>4)*8;                                       \
    const int b_k = ((lane>>3)&1)*8;                                              \
    float acc[4][8][4];                                                           \
    _Pragma("unroll")                                                             \
    for (int i=0;i<4;i++)                                                         \
        _Pragma("unroll")                                                         \
        for (int j=0;j<8;j++)                                                     \
            _Pragma("unroll")                                                     \
            for (int r=0;r<4;r++) acc[i][j][r]=0.f;

#define MMA_BK64_W64(sa, sb)                                                      \
    do {                                                                          \
        _Pragma("unroll")                                                         \
        for (int ks = 0; ks < 4; ks++) {                                          \
            const int kk = ks*16;                                                 \
            uint32_t afr[4][4];                                                   \
            _Pragma("unroll")                                                     \
            for (int mt=0;mt<4;mt++)                                              \
                ldmatrix_x4(afr[mt], (sa) + (uint32_t)((M0 + mt*16 + a_m)*LDS_PAD + kk + a_k)*2); \
            uint32_t bfr[4][4];                                                   \
            _Pragma("unroll")                                                     \
            for (int nh=0;nh<4;nh++)                                              \
                ldmatrix_x4(bfr[nh], (sb) + (uint32_t)((N0 + nh*16 + b_n)*LDS_PAD + kk + b_k)*2); \
            _Pragma("unroll")                                                     \
            for (int mt=0;mt<4;mt++)                                              \
                _Pragma("unroll")                                                 \
                for (int nt=0;nt<8;nt++)                                          \
                    mma16816(acc[mt][nt], afr[mt], &bfr[nt>>1][(nt&1)*2]);        \
        }                                                                         \
    } while (0)

// ---------------- 4) QKV GEMM: 128 threads, warp tile 64x64 -------------------
__global__ void __launch_bounds__(128,2) qkv_mma_kernel() {
    extern __shared__ char smdyn[];
    const int tid = threadIdx.x;
    const int bn  = blockIdx.x;     // 0..23
    const int bm  = blockIdx.y;     // 0..255
    const int m0  = bm*128;
    const __half* Ag = g_a2 + (size_t)m0*KA;
    const __half* Bg = g_wt + (size_t)(bn*128)*KA;
    const uint32_t sbase = smem_u32(smdyn);

    #define QKV_PF(kt) do {                                                       \
        uint32_t sa = sbase + ((kt)%NSTAGE)*STAGE_B;                              \
        fill_tile128(sa,        Ag + (kt)*64, KA, tid);                           \
        fill_tile128(sa+TILE_B, Bg + (kt)*64, KA, tid);                           \
    } while(0)

    WARP_VARS4;
    QKV_PF(0); cp_commit(); QKV_PF(1); cp_commit();

    #pragma unroll 1
    for (int kt = 0; kt < 16; kt++) {
        asm volatile("cp.async.wait_group 1;" ::: "memory");
        __syncthreads();
        if (kt+2 < 16) QKV_PF(kt+2);
        cp_commit();
        const uint32_t sa = sbase + (kt%NSTAGE)*STAGE_B, sb = sa + TILE_B;
        MMA_BK64_W64(sa, sb);
    }
    #undef QKV_PF
    __syncthreads();   // smem about to be reused for epilogue staging

    // ---------------- epilogue ----------------
    const int which = bn >> 3;       // 0=q 1=k 2=v
    const int h     = bn & 7;
    const int b     = m0 >> 13;
    const int bh    = b*Hh + h;
    const int n0b   = m0 & (Nseq-1);
    const int qrow  = lane>>2;
    const int qcol  = (lane&3)*2;

    if (which == 0) {
        #pragma unroll
        for (int mt=0; mt<4; mt++)
            #pragma unroll
            for (int r2=0; r2<2; r2++) {
                const int n_g = n0b + M0 + mt*16 + qrow + r2*8;
                #pragma unroll
                for (int nt=0; nt<8; nt++) {
                    const int e = N0 + nt*8 + qcol;
                    float v0 = acc[mt][nt][r2*2+0] + g_cbias[bn*128 + e];
                    float v1 = acc[mt][nt][r2*2+1] + g_cbias[bn*128 + e + 1];
                    v0 = 1.f/(1.f + __expf(-v0));
                    v1 = 1.f/(1.f + __expf(-v1));
                    __half h0=__float2half_rn(v0), h1=__float2half_rn(v1);
                    __half q0=__float2half_rn(v0-__half2float(h0)),
                           q1=__float2half_rn(v1-__half2float(h1));
                    __half2 hp{h0,h1}, lp{q0,q1};
                    size_t idx = ((size_t)bh*Nseq + n_g)*HDim + e;
                    *(uint32_t*)&g_qhi[idx] = *(uint32_t*)&hp;
                    *(uint32_t*)&g_qlo[idx] = *(uint32_t*)&lp;
                }
            }
    } else {
        // k/v: transpose via smem staging, then coalesced global stores
        __half* sh_hi = (__half*)smdyn;            // [128 e][136]
        __half* sh_lo = sh_hi + 128*136;
        #pragma unroll
        for (int mt=0; mt<4; mt++)
            #pragma unroll
            for (int r2=0; r2<2; r2++) {
                const int n_loc = M0 + mt*16 + qrow + r2*8;
                const int n_g = n0b + n_loc;
                float mfac = 1.f;
                if (which==1) mfac = g_mask[(size_t)b*Nseq + n_g] ? 0.f : 1.f;
                #pragma unroll
                for (int nt=0; nt<8; nt++) {
                    const int e = N0 + nt*8 + qcol;
                    float v0 = acc[mt][nt][r2*2+0] + g_cbias[bn*128 + e];
                    float v1 = acc[mt][nt][r2*2+1] + g_cbias[bn*128 + e + 1];
                    if (which==1) { v0 = tanhf(v0)*mfac; v1 = tanhf(v1)*mfac; }
                    __half h0=__float2half_rn(v0), h1=__float2half_rn(v1);
                    __half q0=__float2half_rn(v0-__half2float(h0)),
                           q1=__float2half_rn(v1-__half2float(h1));
                    sh_hi[e*136 + n_loc]     = h0;
                    sh_hi[(e+1)*136 + n_loc] = h1;
                    sh_lo[e*136 + n_loc]     = q0;
                    sh_lo[(e+1)*136 + n_loc] = q1;
                }
            }
        __syncthreads();
        __half* dh = (which==1) ? g_kth : g_vth;
        __half* dl = (which==1) ? g_ktl : g_vtl;
        const size_t gbase = (size_t)bh*HDim*Nseq + n0b;
        #pragma unroll
        for (int i=0;i<16;i++){
            int c = tid + i*128;        // 2048 chunks of 16B
            int e = c>>4, n = (c&15)*8;
            float4 vh = *(float4*)&sh_hi[e*136 + n];
            float4 vl = *(float4*)&sh_lo[e*136 + n];
            *(float4*)&dh[gbase + (size_t)e*Nseq + n] = vh;
            *(float4*)&dl[gbase + (size_t)e*Nseq + n] = vl;
        }
    }
}

// ---------------- 5) kv partials via mma: kv = k^T v (3-term fp16 split) ------
__global__ void __launch_bounds__(256,2) kv_mma_kernel() {
    extern __shared__ char smdyn[];
    const int tid = threadIdx.x;
    const int ch  = blockIdx.x;     // 0..15 (n-slice of 512)
    const int bh  = blockIdx.y;     // 0..31
    const size_t obh = (size_t)bh*HDim*Nseq;
    const __half* Aseg[3] = { g_kth+obh, g_ktl+obh, g_kth+obh };
    const __half* Bseg[3] = { g_vth+obh, g_vth+obh, g_vtl+obh };
    const uint32_t sbase = smem_u32(smdyn);

    #define KV_PF(kt) do {                                                        \
        uint32_t sa = sbase + ((kt)%NSTAGE)*STAGE_B;                              \
        const int seg = (kt)>>3;                                                  \
        const int nc  = ch*512 + ((kt)&7)*64;                                     \
        fill_tile(sa,        Aseg[seg] + nc, Nseq, tid);                          \
        fill_tile(sa+TILE_B, Bseg[seg] + nc, Nseq, tid);                          \
    } while(0)

    WARP_VARS;
    KV_PF(0); cp_commit(); KV_PF(1); cp_commit();

    #pragma unroll 1
    for (int kt = 0; kt < 24; kt++) {
        asm volatile("cp.async.wait_group 1;" ::: "memory");
        __syncthreads();
        if (kt+2 < 24) KV_PF(kt+2);
        cp_commit();
        const uint32_t sa = sbase + (kt%NSTAGE)*STAGE_B, sb = sa + TILE_B;
        MMA_BK64(sa, sb);
    }
    #undef KV_PF

    const int qrow = lane>>2, qcol = (lane&3)*2;
    float* p = g_kvp + ((size_t)(bh*NCH2 + ch) << 14);
    #pragma unroll
    for (int mt=0; mt<4; mt++)
        #pragma unroll
        for (int r2=0; r2<2; r2++) {
            const int d = M0 + mt*16 + qrow + r2*8;
            #pragma unroll
            for (int nt=0; nt<4; nt++) {
                const int e = N0 + nt*8 + qcol;
                float2 o{acc[mt][nt][r2*2+0], acc[mt][nt][r2*2+1]};
                *(float2*)(p + (size_t)d*HDim + e) = o;
            }
        }
}

// ---------------- 6) reduce partials -> kvt2 [bh][e][hi|hi|lo over d] ---------
__global__ void kv_reduce_kernel() {
    const int bh  = blockIdx.y;
    const int idx = blockIdx.x*256 + threadIdx.x;
    float s = 0.f;
    #pragma unroll
    for (int c = 0; c < NCH2; c++)
        s += g_kvp[((size_t)(bh*NCH2 + c) << 14) + idx];
    const int d = idx >> 7, e = idx & 127;
    __half hi = __float2half_rn(s);
    __half lo = __float2half_rn(s - __half2float(hi));
    __half* base = g_kvt2 + ((size_t)bh*HDim + e)*384 + d;
    base[0]   = hi;
    base[128] = hi;
    base[256] = lo;
}

// ---------------- 7) out = q @ kv via mma (K=384), scatter fp32 ---------------
__global__ void __launch_bounds__(256,2) out_mma_kernel(float* __restrict__ out) {
    extern __shared__ char smdyn[];
    const int tid = threadIdx.x;
    const int mt0 = blockIdx.x;     // 0..63
    const int bh  = blockIdx.y;     // 0..31
    const int m0  = mt0*128;
    const size_t oq = ((size_t)bh*Nseq + m0)*HDim;
    const __half* Aseg[3] = { g_qhi+oq, g_qlo+oq, g_qhi+oq };
    const __half* Bg = g_kvt2 + (size_t)bh*HDim*384;
    const uint32_t sbase = smem_u32(smdyn);

    #define OUT_PF(kt) do {                                                       \
        uint32_t sa = sbase + ((kt)%NSTAGE)*STAGE_B;                              \
        const int seg = (kt)>>1;                                                  \
        fill_tile(sa,        Aseg[seg] + ((kt)&1)*64, HDim, tid);                 \
        fill_tile(sa+TILE_B, Bg + (kt)*64,            384,  tid);                 \
    } while(0)

    WARP_VARS;
    OUT_PF(0); cp_commit(); OUT_PF(1); cp_commit();

    #pragma unroll 1
    for (int kt = 0; kt < 6; kt++) {
        asm volatile("cp.async.wait_group 1;" ::: "memory");
        __syncthreads();
        if (kt+2 < 6) OUT_PF(kt+2);
        cp_commit();
        const uint32_t sa = sbase + (kt%NSTAGE)*STAGE_B, sb = sa + TILE_B;
        MMA_BK64(sa, sb);
    }
    #undef OUT_PF

    const int b = bh>>3, h = bh&7;
    const int qrow = lane>>2, qcol = (lane&3)*2;
    #pragma unroll
    for (int mt=0; mt<4; mt++)
        #pragma unroll
        for (int r2=0; r2<2; r2++) {
            const int n_g = m0 + M0 + mt*16 + qrow + r2*8;
            float* prow_p = out + ((size_t)b*Nseq + n_g)*Dm + h*HDim;
            #pragma unroll
            for (int nt=0; nt<4; nt++) {
                const int e = N0 + nt*8 + qcol;
                float2 o{acc[mt][nt][r2*2+0], acc[mt][nt][r2*2+1]};
                *(float2*)(prow_p + e) = o;
            }
        }
}

// ---------------- launch --------------------------------------------------------
extern "C" void kernel_launch(void* const* d_in, const int* in_sizes, int n_in,
                              void* d_out, int out_size) {
    const float* x = 0; const void* mask = 0; const float* w = 0;
    const float* gamma = 0; const float* beta = 0;
    for (int i = 0; i < n_in; i++) {
        int s = in_sizes[i];
        if      (s == 33554432) x    = (const float*)d_in[i];
        else if (s == 32768)    mask = d_in[i];
        else if (s == 3145728)  w    = (const float*)d_in[i];
        else if (s == 1024)     { if (!gamma) gamma = (const float*)d_in[i];
                                  else        beta  = (const float*)d_in[i]; }
    }
    float* out = (float*)d_out;

    cudaFuncSetAttribute(qkv_mma_kernel, cudaFuncAttributeMaxDynamicSharedMemorySize, SMEM_SZ);
    cudaFuncSetAttribute(kv_mma_kernel,  cudaFuncAttributeMaxDynamicSharedMemorySize, SMEM_SZ);
    cudaFuncSetAttribute(out_mma_kernel, cudaFuncAttributeMaxDynamicSharedMemorySize, SMEM_SZ);

    mask_all_kernel<<<1, 1024>>>((const unsigned int*)mask);            // 1
    ln_a2_kernel<<<Mrows, 256>>>(x);                                    // 2
    build_wt_cb_kernel<<<K3/32, 256>>>(w, gamma, beta);                 // 3
    qkv_mma_kernel<<<dim3(24, 256), 128, SMEM_SZ>>>();                  // 4 (profiled)
    kv_mma_kernel<<<dim3(NCH2, BH), 256, SMEM_SZ>>>();                  // 5
    kv_reduce_kernel<<<dim3(64, BH), 256>>>();                          // 6
    out_mma_kernel<<<dim3(64, BH), 256, SMEM_SZ>>>(out);                // 7
}